// round 1
// baseline (speedup 1.0000x reference)
#include <cuda_runtime.h>
#include <cuda_bf16.h>
#include <cstdint>
#include <cstddef>

// Problem constants
#define BB 32
#define CC 128
#define HH 56
#define WW 56
#define NTOT (BB*CC*HH*WW)       // 12,845,056
#define WSZ  (CC*CC*3*3)         // 147,456
#define HWT  (HH*WW)             // 3136
#define NHW  (BB*HH*WW)          // 100,352

// -------- device scratch (static allocation: allowed) --------
__device__ float g_xq[NTOT];          // quantized input (integer levels), reused for a1q
__device__ float g_y[NTOT];           // conv output buffer (y1, then y2)
__device__ float g_w1t[WSZ];          // quantized w1, transposed [k][co]
__device__ float g_w2t[WSZ];          // quantized w2, transposed [k][co]
__device__ unsigned g_maxbits[4];     // max|.| as float bits: 0=x, 1=w1, 2=w2, 3=a1
__device__ float g_mean[CC];
__device__ float g_rstd[CC];

// -------- init --------
__global__ void init_kernel() {
    if (threadIdx.x < 4) g_maxbits[threadIdx.x] = 0u;
}

// -------- max |.| reduction (deterministic: max is order-independent) --------
__global__ void maxabs_kernel(const float* __restrict__ p, int n, int idx) {
    float m = 0.f;
    for (int i = blockIdx.x * blockDim.x + threadIdx.x; i < n; i += gridDim.x * blockDim.x)
        m = fmaxf(m, fabsf(p[i]));
#pragma unroll
    for (int o = 16; o; o >>= 1) m = fmaxf(m, __shfl_xor_sync(0xFFFFFFFFu, m, o));
    __shared__ float sm[8];
    if ((threadIdx.x & 31) == 0) sm[threadIdx.x >> 5] = m;
    __syncthreads();
    if (threadIdx.x == 0) {
        float mm = sm[0];
#pragma unroll
        for (int k = 1; k < 8; ++k) mm = fmaxf(mm, sm[k]);
        atomicMax(&g_maxbits[idx], __float_as_uint(mm));
    }
}

// -------- quantize x -> integer levels (fp32 holds them exactly) --------
__global__ void quant_x_kernel(const float* __restrict__ x) {
    int i = blockIdx.x * blockDim.x + threadIdx.x;
    if (i >= NTOT) return;
    float s = __uint_as_float(g_maxbits[0]) + 1e-12f;
    float t = x[i] / s;          // mimic jnp: (x / s) * n
    t *= 127.f;
    g_xq[i] = rintf(t);          // round-half-even, matches jnp.round
}

// -------- quantize + transpose weights: OIHW -> [k = ci*9+kh*3+kw][co] --------
__global__ void quant_w_kernel(const float* __restrict__ w, float* __restrict__ wt, int idx) {
    int i = blockIdx.x * blockDim.x + threadIdx.x;
    if (i >= WSZ) return;
    float s = __uint_as_float(g_maxbits[idx]) + 1e-12f;
    int co = i / 1152;
    int k  = i % 1152;
    float t = w[i] / s;
    t *= 127.f;
    wt[k * CC + co] = rintf(t);
}

// -------- conv 3x3, pad 1, stride 1 (quantized-integer domain, exact) --------
// Block tile: 64 co x (8x8 pixels). ci chunks of 16 staged in smem.
// Thread (256/block): cg = tid>>4 (co group, 4 co), pg = tid&15 (4 pixels).
constexpr int BCO = 64;
constexpr int BCI = 16;

__global__ __launch_bounds__(256) void conv3x3(const float* __restrict__ in,
                                               const float* __restrict__ wt,
                                               float* __restrict__ out,
                                               int sIdxA, int sIdxW) {
    __shared__ __align__(16) float Ws[BCI * 9 * BCO];  // [cc][kk][co]  36864 B
    __shared__ float Xs[BCI][10][11];                  // halo, pitch 11  7040 B

    const int tid    = threadIdx.x;
    const int bx     = blockIdx.x;        // 0..48 spatial tile
    const int n      = blockIdx.y;        // image
    const int coBase = blockIdx.z * BCO;  // 0 or 64
    const int ty = bx / 7, tx = bx % 7;
    const int h0 = ty * 8, w0 = tx * 8;
    const int cg  = tid >> 4;             // 0..15
    const int pg  = tid & 15;
    const int ph  = pg >> 1;              // 0..7
    const int pwb = (pg & 1) * 4;         // 0 or 4

    float acc[4][4] = {};

    for (int cb = 0; cb < CC; cb += BCI) {
        // ---- stage weights: 2304 float4, coalesced ----
        for (int e = tid; e < BCI * 9 * 16; e += 256) {
            int row = e >> 4, q = e & 15;         // row = cc*9+kk
            int cc = row / 9, kk = row % 9;
            const float4 v = reinterpret_cast<const float4*>(wt)
                [((size_t)(cb + cc) * 9 + kk) * 32 + (coBase >> 2) + q];
            reinterpret_cast<float4*>(Ws)[e] = v;
        }
        // ---- stage input halo 16 x 10 x 10 (zero-padded) ----
        for (int e = tid; e < BCI * 100; e += 256) {
            int c  = e % 10;
            int r  = (e / 10) % 10;
            int cc = e / 100;
            int gh = h0 - 1 + r, gw = w0 - 1 + c;
            float v = 0.f;
            if ((unsigned)gh < (unsigned)HH && (unsigned)gw < (unsigned)WW)
                v = in[(((size_t)n * CC + cb + cc) * HH + gh) * WW + gw];
            Xs[cc][r][c] = v;
        }
        __syncthreads();

#pragma unroll 2
        for (int cc = 0; cc < BCI; ++cc) {
#pragma unroll
            for (int dh = 0; dh < 3; ++dh) {
                float xr[6];
#pragma unroll
                for (int t = 0; t < 6; ++t) xr[t] = Xs[cc][ph + dh][pwb + t];
#pragma unroll
                for (int dw = 0; dw < 3; ++dw) {
                    const float4 wv = *reinterpret_cast<const float4*>(
                        &Ws[(cc * 9 + dh * 3 + dw) * BCO + cg * 4]);
                    const float wa[4] = {wv.x, wv.y, wv.z, wv.w};
#pragma unroll
                    for (int i = 0; i < 4; ++i)
#pragma unroll
                        for (int j = 0; j < 4; ++j)
                            acc[i][j] = fmaf(wa[i], xr[j + dw], acc[i][j]);
                }
            }
        }
        __syncthreads();
    }

    const float sA = __uint_as_float(g_maxbits[sIdxA]) + 1e-12f;
    const float sW = __uint_as_float(g_maxbits[sIdxW]) + 1e-12f;
    const float scale = (sA / 127.f) * (sW / 127.f);

#pragma unroll
    for (int i = 0; i < 4; ++i) {
        const size_t base =
            (((size_t)n * CC + coBase + cg * 4 + i) * HH + h0 + ph) * WW + w0 + pwb;
#pragma unroll
        for (int j = 0; j < 4; ++j)
            out[base + j] = acc[i][j] * scale;
    }
}

// -------- per-channel BN stats (one block per channel, fp64, deterministic) ----
__global__ void stats_kernel(const float* __restrict__ y) {
    const int c = blockIdx.x;
    const int tid = threadIdx.x;
    double s = 0.0, s2 = 0.0;
    for (int n = 0; n < BB; ++n) {
        const float* p = y + ((size_t)n * CC + c) * HWT;
        for (int i = tid; i < HWT; i += 256) {
            float v = p[i];
            s  += (double)v;
            s2 += (double)v * (double)v;
        }
    }
    __shared__ double sh[256];
    __shared__ double sh2[256];
    sh[tid] = s; sh2[tid] = s2;
    __syncthreads();
    for (int o = 128; o; o >>= 1) {
        if (tid < o) { sh[tid] += sh[tid + o]; sh2[tid] += sh2[tid + o]; }
        __syncthreads();
    }
    if (tid == 0) {
        double mean = sh[0] / (double)NHW;
        double var  = sh2[0] / (double)NHW - mean * mean;
        g_mean[c] = (float)mean;
        g_rstd[c] = (float)(1.0 / sqrt(var + 1e-5));
    }
}

// -------- relu(bn1(y1)) max (for activation quant scale) --------
__global__ void relumax_kernel(const float* __restrict__ y,
                               const float* __restrict__ gamma,
                               const float* __restrict__ beta) {
    float m = 0.f;
    for (int i = blockIdx.x * blockDim.x + threadIdx.x; i < NTOT;
         i += gridDim.x * blockDim.x) {
        int c = (i / HWT) & (CC - 1);
        float a = (y[i] - g_mean[c]) * g_rstd[c] * gamma[c] + beta[c];
        m = fmaxf(m, a);
    }
    m = fmaxf(m, 0.f);
#pragma unroll
    for (int o = 16; o; o >>= 1) m = fmaxf(m, __shfl_xor_sync(0xFFFFFFFFu, m, o));
    __shared__ float sm[8];
    if ((threadIdx.x & 31) == 0) sm[threadIdx.x >> 5] = m;
    __syncthreads();
    if (threadIdx.x == 0) {
        float mm = sm[0];
#pragma unroll
        for (int k = 1; k < 8; ++k) mm = fmaxf(mm, sm[k]);
        atomicMax(&g_maxbits[3], __float_as_uint(mm));
    }
}

// -------- quantize relu(bn1(y1)) -> integer levels into g_xq --------
__global__ void quant_a_kernel(const float* __restrict__ y,
                               const float* __restrict__ gamma,
                               const float* __restrict__ beta) {
    int i = blockIdx.x * blockDim.x + threadIdx.x;
    if (i >= NTOT) return;
    int c = (i / HWT) & (CC - 1);
    float a = (y[i] - g_mean[c]) * g_rstd[c] * gamma[c] + beta[c];
    a = fmaxf(a, 0.f);
    float s = __uint_as_float(g_maxbits[3]) + 1e-12f;
    float t = a / s;
    t *= 127.f;
    g_xq[i] = rintf(t);
}

// -------- final: relu(bn2(y2) + x) --------
__global__ void final_kernel(const float* __restrict__ y,
                             const float* __restrict__ x,
                             const float* __restrict__ gamma,
                             const float* __restrict__ beta,
                             float* __restrict__ out) {
    int i = blockIdx.x * blockDim.x + threadIdx.x;
    if (i >= NTOT) return;
    int c = (i / HWT) & (CC - 1);
    float a = (y[i] - g_mean[c]) * g_rstd[c] * gamma[c] + beta[c] + x[i];
    out[i] = fmaxf(a, 0.f);
}

// ==================== launch ====================
extern "C" void kernel_launch(void* const* d_in, const int* in_sizes, int n_in,
                              void* d_out, int out_size) {
    const float* x      = (const float*)d_in[0];
    const float* w1     = (const float*)d_in[1];
    const float* gamma1 = (const float*)d_in[2];
    const float* beta1  = (const float*)d_in[3];
    const float* w2     = (const float*)d_in[4];
    const float* gamma2 = (const float*)d_in[5];
    const float* beta2  = (const float*)d_in[6];
    float* out = (float*)d_out;

    float* xq  = nullptr; cudaGetSymbolAddress((void**)&xq,  g_xq);
    float* yb  = nullptr; cudaGetSymbolAddress((void**)&yb,  g_y);
    float* w1t = nullptr; cudaGetSymbolAddress((void**)&w1t, g_w1t);
    float* w2t = nullptr; cudaGetSymbolAddress((void**)&w2t, g_w2t);

    const int EW_GRID = (NTOT + 255) / 256;    // 50176
    dim3 cgrid(49, BB, 2);

    init_kernel<<<1, 32>>>();
    maxabs_kernel<<<1024, 256>>>(x,  NTOT, 0);
    maxabs_kernel<<<64,   256>>>(w1, WSZ,  1);
    maxabs_kernel<<<64,   256>>>(w2, WSZ,  2);
    quant_x_kernel<<<EW_GRID, 256>>>(x);
    quant_w_kernel<<<(WSZ + 255) / 256, 256>>>(w1, w1t, 1);
    quant_w_kernel<<<(WSZ + 255) / 256, 256>>>(w2, w2t, 2);

    conv3x3<<<cgrid, 256>>>(xq, w1t, yb, 0, 1);          // y1
    stats_kernel<<<CC, 256>>>(yb);                        // bn1 stats
    relumax_kernel<<<2048, 256>>>(yb, gamma1, beta1);     // max|relu(bn1)|
    quant_a_kernel<<<EW_GRID, 256>>>(yb, gamma1, beta1);  // a1q -> g_xq

    conv3x3<<<cgrid, 256>>>(xq, w2t, yb, 3, 2);          // y2 (overwrites y1)
    stats_kernel<<<CC, 256>>>(yb);                        // bn2 stats
    final_kernel<<<EW_GRID, 256>>>(yb, x, gamma2, beta2, out);
}

// round 2
// speedup vs baseline: 1.7053x; 1.7053x over previous
#include <cuda_runtime.h>
#include <cuda_bf16.h>
#include <cstdint>
#include <cstddef>

// Problem constants
#define BB 32
#define CC 128
#define HH 56
#define WW 56
#define NTOT (BB*CC*HH*WW)       // 12,845,056
#define WSZ  (CC*CC*3*3)         // 147,456
#define HWT  (HH*WW)             // 3136
#define NHW  (BB*HH*WW)          // 100,352
#define NBLK 256                 // stats partial blocks (NHW/NBLK = 392 exactly)

// -------- device scratch --------
__device__ __nv_bfloat16 g_xq[NTOT];   // quantized levels, NHWC (x, then relu(bn1))
__device__ float         g_y[NTOT];    // conv output, NHWC fp32
__device__ __nv_bfloat16 g_w1t[WSZ];   // levels of w1, [kpos][ci][co]
__device__ __nv_bfloat16 g_w2t[WSZ];   // levels of w2, [kpos][ci][co]
__device__ unsigned g_maxbits[4];      // max|.| float bits: 0=x 1=w1 2=w2 3=act1
__device__ float g_mean[CC];
__device__ float g_rstd[CC];
__device__ double g_psum[NBLK][CC];
__device__ double g_psq[NBLK][CC];
__device__ float  g_pmax[NBLK][CC];
__device__ float  g_pmin[NBLK][CC];

// -------- PTX helpers --------
#define LDSM_X4(r0,r1,r2,r3,addr) \
  asm volatile("ldmatrix.sync.aligned.m8n8.x4.shared.b16 {%0,%1,%2,%3}, [%4];" \
    : "=r"(r0),"=r"(r1),"=r"(r2),"=r"(r3) : "r"(addr))
#define LDSM_X2T(r0,r1,addr) \
  asm volatile("ldmatrix.sync.aligned.m8n8.x2.trans.shared.b16 {%0,%1}, [%2];" \
    : "=r"(r0),"=r"(r1) : "r"(addr))
#define MMA_BF16(c,a,b) \
  asm volatile("mma.sync.aligned.m16n8k16.row.col.f32.bf16.bf16.f32 " \
    "{%0,%1,%2,%3}, {%4,%5,%6,%7}, {%8,%9}, {%0,%1,%2,%3};" \
    : "+f"((c)[0]),"+f"((c)[1]),"+f"((c)[2]),"+f"((c)[3]) \
    : "r"((a)[0]),"r"((a)[1]),"r"((a)[2]),"r"((a)[3]),"r"((b)[0]),"r"((b)[1]))

// -------- init --------
__global__ void init_kernel() {
    if (threadIdx.x < 4) g_maxbits[threadIdx.x] = 0u;
}

// -------- max |.| reduction (deterministic) --------
__global__ void maxabs_kernel(const float* __restrict__ p, int n, int idx) {
    float m = 0.f;
    for (int i = blockIdx.x * blockDim.x + threadIdx.x; i < n; i += gridDim.x * blockDim.x)
        m = fmaxf(m, fabsf(p[i]));
#pragma unroll
    for (int o = 16; o; o >>= 1) m = fmaxf(m, __shfl_xor_sync(0xFFFFFFFFu, m, o));
    __shared__ float sm[8];
    if ((threadIdx.x & 31) == 0) sm[threadIdx.x >> 5] = m;
    __syncthreads();
    if (threadIdx.x == 0) {
        float mm = sm[0];
#pragma unroll
        for (int k = 1; k < 8; ++k) mm = fmaxf(mm, sm[k]);
        atomicMax(&g_maxbits[idx], __float_as_uint(mm));
    }
}

// -------- quantize x: NCHW fp32 -> NHWC bf16 levels (smem transpose) --------
__global__ __launch_bounds__(256) void quant_x_t(const float* __restrict__ x,
                                                 __nv_bfloat16* __restrict__ xq) {
    __shared__ float sm[128 * 57];
    const int h = blockIdx.x, n = blockIdx.y, tid = threadIdx.x;
    const float s = __uint_as_float(g_maxbits[0]) + 1e-12f;
    for (int e = tid; e < 7168; e += 256) {
        int c = e / 56, w = e % 56;
        sm[c * 57 + w] = x[((size_t)(n * 128 + c) * 56 + h) * 56 + w];
    }
    __syncthreads();
    const size_t pixbase = (size_t)(n * 56 + h) * 56;
    for (int e = tid; e < 7168; e += 256) {
        int w = e >> 7, c = e & 127;
        float t = __fdiv_rn(sm[c * 57 + w], s) * 127.f;
        xq[(pixbase + w) * 128 + c] = __float2bfloat16(rintf(t));
    }
}

// -------- quantize + reorder weights: OIHW -> [kpos][ci][co] bf16 levels ------
__global__ void quant_w(const float* __restrict__ w, __nv_bfloat16* __restrict__ wt, int idx) {
    int i = blockIdx.x * 256 + threadIdx.x;
    if (i >= WSZ) return;
    float s = __uint_as_float(g_maxbits[idx]) + 1e-12f;
    int co = i / 1152, rem = i % 1152;
    int ci = rem / 9, k = rem % 9;
    wt[(k * 128 + ci) * 128 + co] = __float2bfloat16(rintf(__fdiv_rn(w[i], s) * 127.f));
}

// -------- conv 3x3 via bf16 tensor-core MMA (implicit GEMM, exact) ----------
// Block: 64 pixels (8x8 tile) x 128 co. 8 warps = 2(M) x 4(N), warp tile 32x32.
__global__ __launch_bounds__(256) void conv3x3_mma(const __nv_bfloat16* __restrict__ in,
                                                   const __nv_bfloat16* __restrict__ wt,
                                                   float* __restrict__ out,
                                                   int sIdxA, int sIdxW) {
    __shared__ __align__(16) __nv_bfloat16 Xs[10 * 10 * 16];   // halo [r][c][ci16]
    __shared__ __align__(16) __nv_bfloat16 Bs[9 * 16 * 128];   // [kpos][ci16][co128]

    const int tid = threadIdx.x;
    const int n = blockIdx.y;
    const int ty = blockIdx.x / 7, tx = blockIdx.x % 7;
    const int h0 = ty * 8, w0 = tx * 8;
    const int lane = tid & 31, wid = tid >> 5;
    const int wm = wid >> 2, wn = wid & 3;
    const int g = lane >> 2, tg = lane & 3;

    float acc[2][4][4];
#pragma unroll
    for (int a = 0; a < 2; ++a)
#pragma unroll
        for (int b = 0; b < 4; ++b)
#pragma unroll
            for (int c = 0; c < 4; ++c) acc[a][b][c] = 0.f;

    const uint32_t xs_base = (uint32_t)__cvta_generic_to_shared(Xs);
    const uint32_t bs_base = (uint32_t)__cvta_generic_to_shared(Bs);

    uint32_t aoff[2];
#pragma unroll
    for (int mt = 0; mt < 2; ++mt) {
        int p = wm * 32 + mt * 16 + (lane & 15);
        aoff[mt] = xs_base + (uint32_t)(((p >> 3) * 10 + (p & 7)) * 32 + (lane >> 4) * 16);
    }
    const uint32_t boff = bs_base + (uint32_t)((lane & 15) * 256 + wn * 64);

    for (int cb = 0; cb < 128; cb += 16) {
        // stage all 9 weight tiles for this ci-chunk (coalesced float4)
        {
            int cc = tid >> 4, q = tid & 15;
#pragma unroll
            for (int kk = 0; kk < 9; ++kk)
                reinterpret_cast<float4*>(Bs)[kk * 256 + tid] =
                    reinterpret_cast<const float4*>(wt)[(kk * 128 + cb + cc) * 16 + q];
        }
        // stage input halo 10x10 pixels x 16 ci (NHWC: 16 ci = 32B contiguous)
        if (tid < 200) {
            int pos = tid >> 1, half = tid & 1;
            int r = pos / 10, c = pos % 10;
            int gh = h0 - 1 + r, gw = w0 - 1 + c;
            float4 v = make_float4(0.f, 0.f, 0.f, 0.f);
            if ((unsigned)gh < 56u && (unsigned)gw < 56u)
                v = reinterpret_cast<const float4*>(in)[(((n * 56 + gh) * 56 + gw) << 4) + (cb >> 3) + half];
            reinterpret_cast<float4*>(Xs)[pos * 2 + half] = v;
        }
        __syncthreads();

#pragma unroll
        for (int kk = 0; kk < 9; ++kk) {
            const uint32_t shift = (uint32_t)(((kk / 3) * 10 + (kk % 3)) * 32);
            uint32_t ra[2][4];
#pragma unroll
            for (int mt = 0; mt < 2; ++mt)
                LDSM_X4(ra[mt][0], ra[mt][1], ra[mt][2], ra[mt][3], aoff[mt] + shift);
            uint32_t rb[4][2];
#pragma unroll
            for (int nt = 0; nt < 4; ++nt)
                LDSM_X2T(rb[nt][0], rb[nt][1], boff + kk * 4096 + nt * 16);
#pragma unroll
            for (int mt = 0; mt < 2; ++mt)
#pragma unroll
                for (int nt = 0; nt < 4; ++nt)
                    MMA_BF16(acc[mt][nt], ra[mt], rb[nt]);
        }
        __syncthreads();
    }

    const float sA = __uint_as_float(g_maxbits[sIdxA]) + 1e-12f;
    const float sW = __uint_as_float(g_maxbits[sIdxW]) + 1e-12f;
    const float scale = (sA * (1.f / 127.f)) * (sW * (1.f / 127.f));

#pragma unroll
    for (int mt = 0; mt < 2; ++mt) {
#pragma unroll
        for (int half = 0; half < 2; ++half) {
            int pp = wm * 32 + mt * 16 + g + half * 8;
            int gh = h0 + (pp >> 3), gw = w0 + (pp & 7);
            size_t base = ((size_t)((n * 56 + gh) * 56 + gw)) * 128;
#pragma unroll
            for (int nt = 0; nt < 4; ++nt) {
                int co = wn * 32 + nt * 8 + tg * 2;
                float2 v = make_float2(acc[mt][nt][half * 2 + 0] * scale,
                                       acc[mt][nt][half * 2 + 1] * scale);
                *reinterpret_cast<float2*>(&out[base + co]) = v;
            }
        }
    }
}

// -------- BN stats stage 1: per-block partial sum/sumsq/min/max (NHWC) -------
__global__ __launch_bounds__(256) void stats_part(const float* __restrict__ y) {
    const int b = blockIdx.x, tid = threadIdx.x;
    const int ch = tid & 127, half = tid >> 7;
    const int PPB = NHW / NBLK;  // 392
    const size_t start = (size_t)b * PPB;
    double s = 0.0, s2 = 0.0;
    float mx = -3.4e38f, mn = 3.4e38f;
    for (int i = half; i < PPB; i += 2) {
        float v = y[(start + i) * 128 + ch];
        s += (double)v; s2 += (double)v * (double)v;
        mx = fmaxf(mx, v); mn = fminf(mn, v);
    }
    __shared__ double sh[256], sh2[256];
    __shared__ float shx[256], shn[256];
    sh[tid] = s; sh2[tid] = s2; shx[tid] = mx; shn[tid] = mn;
    __syncthreads();
    if (half == 0) {
        g_psum[b][ch] = sh[tid] + sh[tid + 128];
        g_psq[b][ch]  = sh2[tid] + sh2[tid + 128];
        g_pmax[b][ch] = fmaxf(shx[tid], shx[tid + 128]);
        g_pmin[b][ch] = fminf(shn[tid], shn[tid + 128]);
    }
}

// -------- BN stats stage 2 + (optional) activation amax from channel extrema --
__global__ void stats_final(const float* __restrict__ gamma, const float* __restrict__ beta,
                            int computeAmax) {
    const int c = threadIdx.x;  // 128 threads
    double s = 0.0, s2 = 0.0;
    float mx = -3.4e38f, mn = 3.4e38f;
    for (int b = 0; b < NBLK; ++b) {
        s += g_psum[b][c]; s2 += g_psq[b][c];
        mx = fmaxf(mx, g_pmax[b][c]); mn = fminf(mn, g_pmin[b][c]);
    }
    double mean = s / (double)NHW;
    double var = s2 / (double)NHW - mean * mean;
    float meanf = (float)mean;
    float rstdf = (float)(1.0 / sqrt(var + 1e-5));
    g_mean[c] = meanf; g_rstd[c] = rstdf;
    __shared__ float red[128];
    float am = 0.f;
    if (computeAmax) {
        float gb = rstdf * gamma[c];
        float a1 = (mx - meanf) * gb + beta[c];
        float a2 = (mn - meanf) * gb + beta[c];
        am = fmaxf(fmaxf(a1, a2), 0.f);  // BN monotonic: extrema give the max
    }
    red[c] = am;
    __syncthreads();
    for (int o = 64; o; o >>= 1) {
        if (c < o) red[c] = fmaxf(red[c], red[c + o]);
        __syncthreads();
    }
    if (c == 0 && computeAmax) g_maxbits[3] = __float_as_uint(red[0]);
}

// -------- bn1 + relu + quantize -> NHWC bf16 levels --------
__global__ void quant_a(const float* __restrict__ y, const float* __restrict__ gamma,
                        const float* __restrict__ beta, __nv_bfloat16* __restrict__ xq) {
    int i = blockIdx.x * 256 + threadIdx.x;
    int c = i & 127;
    float v = y[i];
    float a = fmaxf((v - g_mean[c]) * (g_rstd[c] * __ldg(&gamma[c])) + __ldg(&beta[c]), 0.f);
    float s = __uint_as_float(g_maxbits[3]) + 1e-12f;
    xq[i] = __float2bfloat16(rintf(__fdiv_rn(a, s) * 127.f));
}

// -------- final: relu(bn2(y2) + x), NHWC -> NCHW via smem --------
__global__ __launch_bounds__(256) void final_t(const float* __restrict__ y,
                                               const float* __restrict__ x,
                                               const float* __restrict__ gamma,
                                               const float* __restrict__ beta,
                                               float* __restrict__ out) {
    __shared__ float sm[56 * 129];
    const int h = blockIdx.x, n = blockIdx.y, tid = threadIdx.x;
    const size_t pixbase = (size_t)(n * 56 + h) * 56;
    for (int e = tid; e < 7168; e += 256) {
        int w = e >> 7, c = e & 127;
        sm[w * 129 + c] = y[(pixbase + w) * 128 + c];
    }
    __syncthreads();
    for (int e = tid; e < 7168; e += 256) {
        int c = e / 56, w = e % 56;
        size_t o = ((size_t)(n * 128 + c) * 56 + h) * 56 + w;
        float a = (sm[w * 129 + c] - g_mean[c]) * (g_rstd[c] * gamma[c]) + beta[c] + x[o];
        out[o] = fmaxf(a, 0.f);
    }
}

// ==================== launch ====================
extern "C" void kernel_launch(void* const* d_in, const int* in_sizes, int n_in,
                              void* d_out, int out_size) {
    const float* x      = (const float*)d_in[0];
    const float* w1     = (const float*)d_in[1];
    const float* gamma1 = (const float*)d_in[2];
    const float* beta1  = (const float*)d_in[3];
    const float* w2     = (const float*)d_in[4];
    const float* gamma2 = (const float*)d_in[5];
    const float* beta2  = (const float*)d_in[6];
    float* out = (float*)d_out;

    __nv_bfloat16* xq  = nullptr; cudaGetSymbolAddress((void**)&xq,  g_xq);
    float*         yb  = nullptr; cudaGetSymbolAddress((void**)&yb,  g_y);
    __nv_bfloat16* w1t = nullptr; cudaGetSymbolAddress((void**)&w1t, g_w1t);
    __nv_bfloat16* w2t = nullptr; cudaGetSymbolAddress((void**)&w2t, g_w2t);

    init_kernel<<<1, 32>>>();
    maxabs_kernel<<<1024, 256>>>(x,  NTOT, 0);
    maxabs_kernel<<<64,   256>>>(w1, WSZ,  1);
    maxabs_kernel<<<64,   256>>>(w2, WSZ,  2);
    quant_x_t<<<dim3(56, 32), 256>>>(x, xq);
    quant_w<<<576, 256>>>(w1, w1t, 1);
    quant_w<<<576, 256>>>(w2, w2t, 2);

    conv3x3_mma<<<dim3(49, 32), 256>>>(xq, w1t, yb, 0, 1);   // y1 (NHWC)
    stats_part<<<NBLK, 256>>>(yb);
    stats_final<<<1, 128>>>(gamma1, beta1, 1);               // bn1 stats + act amax
    quant_a<<<NTOT / 256, 256>>>(yb, gamma1, beta1, xq);     // levels of relu(bn1)

    conv3x3_mma<<<dim3(49, 32), 256>>>(xq, w2t, yb, 3, 2);   // y2 (NHWC)
    stats_part<<<NBLK, 256>>>(yb);
    stats_final<<<1, 128>>>(gamma2, beta2, 0);               // bn2 stats
    final_t<<<dim3(56, 32), 256>>>(yb, x, gamma2, beta2, out);
}

// round 4
// speedup vs baseline: 2.9554x; 1.7331x over previous
#include <cuda_runtime.h>
#include <cuda_bf16.h>
#include <cstdint>
#include <cstddef>

// Problem constants
#define BB 32
#define CC 128
#define HH 56
#define WW 56
#define NTOT (BB*CC*HH*WW)       // 12,845,056
#define WSZ  (CC*CC*3*3)         // 147,456
#define HWT  (HH*WW)             // 3136
#define NHW  (BB*HH*WW)          // 100,352 = 784 * 128
#define NBLK 256

// -------- device scratch --------
__device__ __align__(16) __nv_bfloat16 g_xq[NTOT];   // levels, NHWC
__device__ __align__(16) float         g_y[NTOT];    // conv out, NHWC fp32
__device__ __align__(16) __nv_bfloat16 g_w1t[WSZ];   // levels w1, [k][ci][co]
__device__ __align__(16) __nv_bfloat16 g_w2t[WSZ];   // levels w2, [k][ci][co]
__device__ unsigned g_maxbits[4];      // 0=x 1=w1 2=w2 3=act1
__device__ float g_mean[CC];
__device__ float g_rstd[CC];
__device__ double g_psum[NBLK][CC];
__device__ double g_psq[NBLK][CC];
__device__ float  g_pmax[NBLK][CC];
__device__ float  g_pmin[NBLK][CC];

// -------- PTX helpers --------
__device__ __forceinline__ uint32_t smem_u32(const void* p) {
    uint32_t a;
    asm("{ .reg .u64 t; cvta.to.shared.u64 t, %1; cvt.u32.u64 %0, t; }" : "=r"(a) : "l"(p));
    return a;
}
#define LDSM_X4(r0,r1,r2,r3,addr) \
  asm volatile("ldmatrix.sync.aligned.m8n8.x4.shared.b16 {%0,%1,%2,%3}, [%4];" \
    : "=r"(r0),"=r"(r1),"=r"(r2),"=r"(r3) : "r"(addr))
#define LDSM_X4T(r0,r1,r2,r3,addr) \
  asm volatile("ldmatrix.sync.aligned.m8n8.x4.trans.shared.b16 {%0,%1,%2,%3}, [%4];" \
    : "=r"(r0),"=r"(r1),"=r"(r2),"=r"(r3) : "r"(addr))
#define MMA_BF16(c,a0,a1,a2,a3,b0,b1) \
  asm volatile("mma.sync.aligned.m16n8k16.row.col.f32.bf16.bf16.f32 " \
    "{%0,%1,%2,%3}, {%4,%5,%6,%7}, {%8,%9}, {%0,%1,%2,%3};" \
    : "+f"((c)[0]),"+f"((c)[1]),"+f"((c)[2]),"+f"((c)[3]) \
    : "r"(a0),"r"(a1),"r"(a2),"r"(a3),"r"(b0),"r"(b1))
#define CP_ASYNC(dst, src, sz) \
  asm volatile("cp.async.cg.shared.global [%0], [%1], 16, %2;" \
    :: "r"(dst), "l"(src), "r"(sz) : "memory")
#define CP_COMMIT() asm volatile("cp.async.commit_group;" ::: "memory")
#define CP_WAIT(n)  asm volatile("cp.async.wait_group %0;" :: "n"(n) : "memory")

// SMEM: A0@0 A1@16384 B0@32768 B1@49152, each 16KB. Total 64KB dynamic.
#define SMEM_TOTAL 65536

// ================= conv via pipelined mma.sync =================
// Tile: 128 flattened pixels x 128 co. K = 9*128 in 18 stages of 64 ci.
// 8 warps = 4(M) x 2(N); warp tile 32 x 64.
__global__ __launch_bounds__(256, 2) void conv_mma(const __nv_bfloat16* __restrict__ in,
                                                   const __nv_bfloat16* __restrict__ wt,
                                                   float* __restrict__ out,
                                                   int sIdxA, int sIdxW) {
    extern __shared__ char smem[];
    const uint32_t sb = smem_u32(smem);
    const int tid = threadIdx.x, lane = tid & 31, wid = tid >> 5;
    const int wm = wid & 3, wn = wid >> 2;
    const int tileBase = blockIdx.x * 128;

    // ---- loader precompute (4 A-pixels + 4 B-rows per thread per stage) ----
    int pn[4], phh[4], pww[4];
#pragma unroll
    for (int i = 0; i < 4; ++i) {
        int p = tileBase + (tid >> 3) + 32 * i;
        pn[i] = p / HWT; int r = p % HWT;
        phh[i] = r / WW; pww[i] = r % WW;
    }
    const uint32_t aDst0 = ((uint32_t)(tid >> 3) << 7)
                         + ((uint32_t)(((tid & 7) ^ ((tid >> 3) & 7))) << 4);
    const uint32_t bDst0 = ((uint32_t)(tid >> 4) << 8)
                         + ((uint32_t)(((tid & 15) ^ ((tid >> 4) & 7))) << 4);
    const int aCi = (tid & 7) * 8;      // ci offset within 64-chunk
    const int bCo = (tid & 15) * 8;
    const int bRow0 = tid >> 4;

    // ---- mma addressing precompute ----
    const int ar = lane & 15, ax = lane >> 4, r7 = lane & 7;
    uint32_t aRowOff[2];
#pragma unroll
    for (int mt = 0; mt < 2; ++mt)
        aRowOff[mt] = (uint32_t)((wm * 32 + mt * 16 + ar) << 7);
    const uint32_t bRowOff = (uint32_t)((lane & 15) << 8);

    float acc[2][8][4];
#pragma unroll
    for (int a = 0; a < 2; ++a)
#pragma unroll
        for (int b = 0; b < 8; ++b)
#pragma unroll
            for (int c = 0; c < 4; ++c) acc[a][b][c] = 0.f;

    // ---- stage loader ----
    auto load_stage = [&](int s) {
        const int kk = s >> 1, half = s & 1;
        const int dh = kk / 3 - 1, dw = kk % 3 - 1;
        const uint32_t abuf = sb + (uint32_t)((s & 1) * 16384);
        const uint32_t bbuf = sb + 32768u + (uint32_t)((s & 1) * 16384);
#pragma unroll
        for (int i = 0; i < 4; ++i) {
            int hs = phh[i] + dh, ws = pww[i] + dw;
            uint32_t ok = ((unsigned)hs < (unsigned)HH && (unsigned)ws < (unsigned)WW) ? 16u : 0u;
            const __nv_bfloat16* src = ok
                ? in + ((size_t)(pn[i] * HWT + hs * WW + ws) * 128 + half * 64 + aCi)
                : in;
            CP_ASYNC(abuf + aDst0 + (uint32_t)(i * 4096), src, ok);
        }
        const __nv_bfloat16* wsrc = wt + ((size_t)(kk * 128 + half * 64 + bRow0) * 128 + bCo);
#pragma unroll
        for (int i = 0; i < 4; ++i)
            CP_ASYNC(bbuf + bDst0 + (uint32_t)(i * 4096), wsrc + (size_t)i * 16 * 128, 16u);
        CP_COMMIT();
    };

    load_stage(0);
    for (int s = 0; s < 18; ++s) {
        if (s < 17) { load_stage(s + 1); CP_WAIT(1); }
        else        { CP_WAIT(0); }
        __syncthreads();

        const uint32_t abuf = sb + (uint32_t)((s & 1) * 16384);
        const uint32_t bbuf = sb + 32768u + (uint32_t)((s & 1) * 16384);
#pragma unroll
        for (int ks = 0; ks < 4; ++ks) {
            uint32_t a0[4], a1[4];
            LDSM_X4(a0[0], a0[1], a0[2], a0[3],
                    abuf + aRowOff[0] + ((uint32_t)(((ks * 2 + ax) ^ r7)) << 4));
            LDSM_X4(a1[0], a1[1], a1[2], a1[3],
                    abuf + aRowOff[1] + ((uint32_t)(((ks * 2 + ax) ^ r7)) << 4));
            uint32_t bfrag[4][4];
            const uint32_t brow = bbuf + (uint32_t)(ks * 16 * 256) + bRowOff;
#pragma unroll
            for (int nt2 = 0; nt2 < 4; ++nt2)
                LDSM_X4T(bfrag[nt2][0], bfrag[nt2][1], bfrag[nt2][2], bfrag[nt2][3],
                         brow + ((uint32_t)(((wn * 8 + nt2 * 2 + ax) ^ r7)) << 4));
#pragma unroll
            for (int nt = 0; nt < 8; ++nt) {
                const uint32_t* bp = &bfrag[nt >> 1][(nt & 1) * 2];
                MMA_BF16(acc[0][nt], a0[0], a0[1], a0[2], a0[3], bp[0], bp[1]);
                MMA_BF16(acc[1][nt], a1[0], a1[1], a1[2], a1[3], bp[0], bp[1]);
            }
        }
        __syncthreads();
    }

    const float sA = __uint_as_float(g_maxbits[sIdxA]) + 1e-12f;
    const float sW = __uint_as_float(g_maxbits[sIdxW]) + 1e-12f;
    const float scale = (sA * (1.f / 127.f)) * (sW * (1.f / 127.f));

    const int g = lane >> 2, tg = lane & 3;
#pragma unroll
    for (int mt = 0; mt < 2; ++mt) {
#pragma unroll
        for (int half = 0; half < 2; ++half) {
            int prow = wm * 32 + mt * 16 + half * 8 + g;
            float* dst = out + (size_t)(tileBase + prow) * 128 + wn * 64 + tg * 2;
#pragma unroll
            for (int nt = 0; nt < 8; ++nt) {
                float2 v = make_float2(acc[mt][nt][half * 2 + 0] * scale,
                                       acc[mt][nt][half * 2 + 1] * scale);
                *reinterpret_cast<float2*>(dst + nt * 8) = v;
            }
        }
    }
}

// ================= small kernels =================
__global__ void init_kernel() {
    if (threadIdx.x < 4) g_maxbits[threadIdx.x] = 0u;
}

__global__ void maxabs_kernel(const float* __restrict__ p, int n, int idx) {
    float m = 0.f;
    for (int i = blockIdx.x * blockDim.x + threadIdx.x; i < n; i += gridDim.x * blockDim.x)
        m = fmaxf(m, fabsf(p[i]));
#pragma unroll
    for (int o = 16; o; o >>= 1) m = fmaxf(m, __shfl_xor_sync(0xFFFFFFFFu, m, o));
    __shared__ float sm[8];
    if ((threadIdx.x & 31) == 0) sm[threadIdx.x >> 5] = m;
    __syncthreads();
    if (threadIdx.x == 0) {
        float mm = sm[0];
#pragma unroll
        for (int k = 1; k < 8; ++k) mm = fmaxf(mm, sm[k]);
        atomicMax(&g_maxbits[idx], __float_as_uint(mm));
    }
}

__global__ __launch_bounds__(256) void quant_x_t(const float* __restrict__ x,
                                                 __nv_bfloat16* __restrict__ xq) {
    __shared__ float sm[128 * 57];
    const int h = blockIdx.x, n = blockIdx.y, tid = threadIdx.x;
    const float s = __uint_as_float(g_maxbits[0]) + 1e-12f;
    for (int e = tid; e < 7168; e += 256) {
        int c = e / 56, w = e % 56;
        sm[c * 57 + w] = x[((size_t)(n * 128 + c) * 56 + h) * 56 + w];
    }
    __syncthreads();
    const size_t pixbase = (size_t)(n * 56 + h) * 56;
    for (int e = tid; e < 7168; e += 256) {
        int w = e >> 7, c = e & 127;
        float t = __fdiv_rn(sm[c * 57 + w], s) * 127.f;
        xq[(pixbase + w) * 128 + c] = __float2bfloat16(rintf(t));
    }
}

// OIHW -> [k][ci][co] bf16 levels
__global__ void quant_w(const float* __restrict__ w, __nv_bfloat16* __restrict__ wt, int idx) {
    int i = blockIdx.x * 256 + threadIdx.x;
    if (i >= WSZ) return;
    float s = __uint_as_float(g_maxbits[idx]) + 1e-12f;
    int co = i / 1152, rem = i % 1152;
    int ci = rem / 9, k = rem % 9;
    wt[((size_t)k * 128 + ci) * 128 + co] = __float2bfloat16(rintf(__fdiv_rn(w[i], s) * 127.f));
}

__global__ __launch_bounds__(256) void stats_part(const float* __restrict__ y) {
    const int b = blockIdx.x, tid = threadIdx.x;
    const int ch = tid & 127, half = tid >> 7;
    const int PPB = NHW / NBLK;  // 392
    const size_t start = (size_t)b * PPB;
    double s = 0.0, s2 = 0.0;
    float mx = -3.4e38f, mn = 3.4e38f;
    for (int i = half; i < PPB; i += 2) {
        float v = y[(start + i) * 128 + ch];
        s += (double)v; s2 += (double)v * (double)v;
        mx = fmaxf(mx, v); mn = fminf(mn, v);
    }
    __shared__ double sh[256], sh2[256];
    __shared__ float shx[256], shn[256];
    sh[tid] = s; sh2[tid] = s2; shx[tid] = mx; shn[tid] = mn;
    __syncthreads();
    if (half == 0) {
        g_psum[b][ch] = sh[tid] + sh[tid + 128];
        g_psq[b][ch]  = sh2[tid] + sh2[tid + 128];
        g_pmax[b][ch] = fmaxf(shx[tid], shx[tid + 128]);
        g_pmin[b][ch] = fminf(shn[tid], shn[tid + 128]);
    }
}

__global__ void stats_final(const float* __restrict__ gamma, const float* __restrict__ beta,
                            int computeAmax) {
    const int c = threadIdx.x;  // 128 threads
    double s = 0.0, s2 = 0.0;
    float mx = -3.4e38f, mn = 3.4e38f;
    for (int b = 0; b < NBLK; ++b) {
        s += g_psum[b][c]; s2 += g_psq[b][c];
        mx = fmaxf(mx, g_pmax[b][c]); mn = fminf(mn, g_pmin[b][c]);
    }
    double mean = s / (double)NHW;
    double var = s2 / (double)NHW - mean * mean;
    float meanf = (float)mean;
    float rstdf = (float)(1.0 / sqrt(var + 1e-5));
    g_mean[c] = meanf; g_rstd[c] = rstdf;
    __shared__ float red[128];
    float am = 0.f;
    if (computeAmax) {
        float gb = rstdf * gamma[c];
        float a1 = (mx - meanf) * gb + beta[c];
        float a2 = (mn - meanf) * gb + beta[c];
        am = fmaxf(fmaxf(a1, a2), 0.f);
    }
    red[c] = am;
    __syncthreads();
    for (int o = 64; o; o >>= 1) {
        if (c < o) red[c] = fmaxf(red[c], red[c + o]);
        __syncthreads();
    }
    if (c == 0 && computeAmax) g_maxbits[3] = __float_as_uint(red[0]);
}

__global__ void quant_a(const float* __restrict__ y, const float* __restrict__ gamma,
                        const float* __restrict__ beta, __nv_bfloat16* __restrict__ xq) {
    int i = blockIdx.x * 256 + threadIdx.x;
    int c = i & 127;
    float a = fmaxf((y[i] - g_mean[c]) * (g_rstd[c] * __ldg(&gamma[c])) + __ldg(&beta[c]), 0.f);
    float s = __uint_as_float(g_maxbits[3]) + 1e-12f;
    xq[i] = __float2bfloat16(rintf(__fdiv_rn(a, s) * 127.f));
}

__global__ __launch_bounds__(256) void final_t(const float* __restrict__ y,
                                               const float* __restrict__ x,
                                               const float* __restrict__ gamma,
                                               const float* __restrict__ beta,
                                               float* __restrict__ out) {
    __shared__ float sm[56 * 129];
    const int h = blockIdx.x, n = blockIdx.y, tid = threadIdx.x;
    const size_t pixbase = (size_t)(n * 56 + h) * 56;
    for (int e = tid; e < 7168; e += 256) {
        int w = e >> 7, c = e & 127;
        sm[w * 129 + c] = y[(pixbase + w) * 128 + c];
    }
    __syncthreads();
    for (int e = tid; e < 7168; e += 256) {
        int c = e / 56, w = e % 56;
        size_t o = ((size_t)(n * 128 + c) * 56 + h) * 56 + w;
        float a = (sm[w * 129 + c] - g_mean[c]) * (g_rstd[c] * gamma[c]) + beta[c] + x[o];
        out[o] = fmaxf(a, 0.f);
    }
}

// ==================== launch ====================
extern "C" void kernel_launch(void* const* d_in, const int* in_sizes, int n_in,
                              void* d_out, int out_size) {
    const float* x      = (const float*)d_in[0];
    const float* w1     = (const float*)d_in[1];
    const float* gamma1 = (const float*)d_in[2];
    const float* beta1  = (const float*)d_in[3];
    const float* w2     = (const float*)d_in[4];
    const float* gamma2 = (const float*)d_in[5];
    const float* beta2  = (const float*)d_in[6];
    float* out = (float*)d_out;

    __nv_bfloat16* xq  = nullptr; cudaGetSymbolAddress((void**)&xq,  g_xq);
    float*         yb  = nullptr; cudaGetSymbolAddress((void**)&yb,  g_y);
    __nv_bfloat16* w1t = nullptr; cudaGetSymbolAddress((void**)&w1t, g_w1t);
    __nv_bfloat16* w2t = nullptr; cudaGetSymbolAddress((void**)&w2t, g_w2t);

    cudaFuncSetAttribute(conv_mma, cudaFuncAttributeMaxDynamicSharedMemorySize, SMEM_TOTAL);

    init_kernel<<<1, 32>>>();
    maxabs_kernel<<<1024, 256>>>(x,  NTOT, 0);
    maxabs_kernel<<<64,   256>>>(w1, WSZ,  1);
    maxabs_kernel<<<64,   256>>>(w2, WSZ,  2);
    quant_x_t<<<dim3(56, 32), 256>>>(x, xq);
    quant_w<<<576, 256>>>(w1, w1t, 1);
    quant_w<<<576, 256>>>(w2, w2t, 2);

    conv_mma<<<NHW / 128, 256, SMEM_TOTAL>>>(xq, w1t, yb, 0, 1);   // y1 (NHWC)
    stats_part<<<NBLK, 256>>>(yb);
    stats_final<<<1, 128>>>(gamma1, beta1, 1);
    quant_a<<<NTOT / 256, 256>>>(yb, gamma1, beta1, xq);

    conv_mma<<<NHW / 128, 256, SMEM_TOTAL>>>(xq, w2t, yb, 3, 2);   // y2 (NHWC)
    stats_part<<<NBLK, 256>>>(yb);
    stats_final<<<1, 128>>>(gamma2, beta2, 0);
    final_t<<<dim3(56, 32), 256>>>(yb, x, gamma2, beta2, out);
}